// round 1
// baseline (speedup 1.0000x reference)
#include <cuda_runtime.h>
#include <cstdint>

// Problem constants
#define SQ      4096
#define HH      16
#define DD      64
#define HALFW   128
#define TQ      32                   // query rows per block
#define SPAN    (TQ + 2*HALFW)       // 288 key columns covered per block
#define KSTR    68                   // padded row stride (floats) for K/V in smem (bank-conflict-free, 16B aligned)
#define PSTR    292                  // padded row stride for P (prob) buffer
#define THREADS 256

// Shared memory layout (in floats)
#define Q_OFF   0
#define K_OFF   (TQ*DD)                  // 2048
#define V_OFF   (K_OFF + SPAN*KSTR)      // 21632
#define P_OFF   (V_OFF + SPAN*KSTR)      // 41216
#define SMEM_FLOATS (P_OFF + TQ*PSTR)    // 50560
#define SMEM_BYTES  (SMEM_FLOATS * 4)    // 202240 bytes

__global__ __launch_bounds__(THREADS, 1)
void win_attn_kernel(const float* __restrict__ q,
                     const float* __restrict__ k,
                     const float* __restrict__ v,
                     float* __restrict__ out,   // [H, S, D]
                     float* __restrict__ attn)  // [H, S, S] (may be null)
{
    extern __shared__ float sm[];
    const int tile = blockIdx.x;           // 0..127
    const int h    = blockIdx.y;           // 0..15
    const int t0   = tile * TQ;
    const int span_start = t0 - HALFW;     // global col of span index 0 (multiple of 32)
    const int tid  = threadIdx.x;

    // ---------------- Load Q tile (contiguous copy) ----------------
    {
        const float4* qg = reinterpret_cast<const float4*>(q) + (size_t)(h * SQ + t0) * (DD / 4);
        float4* Qs4 = reinterpret_cast<float4*>(sm + Q_OFF);
        #pragma unroll 1
        for (int idx = tid; idx < TQ * (DD / 4); idx += THREADS)
            Qs4[idx] = qg[idx];
    }

    // ---------------- Load K/V span (zero-fill outside [0,S)) ----------------
    {
        const float4* kg = reinterpret_cast<const float4*>(k) + (size_t)h * SQ * (DD / 4);
        const float4* vg = reinterpret_cast<const float4*>(v) + (size_t)h * SQ * (DD / 4);
        #pragma unroll 1
        for (int idx = tid; idx < SPAN * (DD / 4); idx += THREADS) {
            int c  = idx >> 4;           // span row
            int d4 = idx & 15;           // float4 within row
            int j  = span_start + c;     // global key index
            float4 kv = make_float4(0.f, 0.f, 0.f, 0.f);
            float4 vv = kv;
            if (j >= 0 && j < SQ) {
                kv = kg[j * 16 + d4];
                vv = vg[j * 16 + d4];
            }
            *reinterpret_cast<float4*>(sm + K_OFF + c * KSTR + d4 * 4) = kv;
            *reinterpret_cast<float4*>(sm + V_OFF + c * KSTR + d4 * 4) = vv;
        }
    }

    // ---------------- Zero P buffer ----------------
    {
        const float4 z4 = make_float4(0.f, 0.f, 0.f, 0.f);
        float4* Ps4 = reinterpret_cast<float4*>(sm + P_OFF);
        #pragma unroll 1
        for (int idx = tid; idx < (TQ * PSTR) / 4; idx += THREADS)
            Ps4[idx] = z4;
    }
    __syncthreads();

    // ---------------- Phase A: banded QK + softmax (warp per 4 rows) ----------------
    {
        const int w  = tid >> 5;
        const int l  = tid & 31;
        const int r0 = w * 4;            // this warp's first local row

        float s[4][9];
        #pragma unroll
        for (int rr = 0; rr < 4; rr++)
            #pragma unroll
            for (int u = 0; u < 9; u++) s[rr][u] = 0.f;

        int cidx[9];                     // clamped span indices (clamp keeps smem reads in-bounds; masked later)
        #pragma unroll
        for (int u = 0; u < 9; u++) {
            int c = r0 + l + 32 * u;
            cidx[u] = (c < SPAN) ? c : (SPAN - 1);
        }

        #pragma unroll 4
        for (int d4 = 0; d4 < 16; d4++) {
            float4 qv[4];
            #pragma unroll
            for (int rr = 0; rr < 4; rr++)
                qv[rr] = *reinterpret_cast<const float4*>(sm + Q_OFF + (r0 + rr) * DD + d4 * 4);
            #pragma unroll
            for (int u = 0; u < 9; u++) {
                float4 kv = *reinterpret_cast<const float4*>(sm + K_OFF + cidx[u] * KSTR + d4 * 4);
                #pragma unroll
                for (int rr = 0; rr < 4; rr++) {
                    s[rr][u] += qv[rr].x * kv.x;
                    s[rr][u] += qv[rr].y * kv.y;
                    s[rr][u] += qv[rr].z * kv.z;
                    s[rr][u] += qv[rr].w * kv.w;
                }
            }
        }

        #pragma unroll
        for (int rr = 0; rr < 4; rr++) {
            const int r = r0 + rr;
            float sv[9];
            float m = -3.0e38f;
            #pragma unroll
            for (int u = 0; u < 9; u++) {
                int c   = r0 + l + 32 * u;
                int off = c - r;                  // position within row window [0,256]
                int j   = span_start + c;
                bool valid = (off >= 0) & (off <= 2 * HALFW) & (j >= 0) & (j < SQ);
                sv[u] = valid ? s[rr][u] * 0.125f : -1.0e30f;
                m = fmaxf(m, sv[u]);
            }
            #pragma unroll
            for (int o = 16; o > 0; o >>= 1)
                m = fmaxf(m, __shfl_xor_sync(0xffffffffu, m, o));
            float sum = 0.f;
            #pragma unroll
            for (int u = 0; u < 9; u++) {
                sv[u] = __expf(sv[u] - m);        // invalid -> exp(-1e30) == 0
                sum += sv[u];
            }
            #pragma unroll
            for (int o = 16; o > 0; o >>= 1)
                sum += __shfl_xor_sync(0xffffffffu, sum, o);
            const float inv = __fdividef(1.f, sum);
            #pragma unroll
            for (int u = 0; u < 9; u++) {
                int c   = r0 + l + 32 * u;
                int off = c - r;
                int j   = span_start + c;
                if ((off >= 0) & (off <= 2 * HALFW) & (j >= 0) & (j < SQ))
                    sm[P_OFF + r * PSTR + c] = sv[u] * inv;
            }
        }
    }
    __syncthreads();

    // ---------------- Phase B: out = P * V  (thread computes 2 rows x 4 cols) ----------------
    {
        const int rp = tid >> 4;         // 0..15  -> rows 2rp, 2rp+1
        const int cq = tid & 15;         // 0..15  -> cols 4cq..4cq+3
        const int R0 = rp * 2;
        const int R1 = R0 + 1;
        float4 a0 = make_float4(0.f, 0.f, 0.f, 0.f);
        float4 a1 = a0;
        const float* pr0 = sm + P_OFF + R0 * PSTR;
        const float* pr1 = sm + P_OFF + R1 * PSTR;
        #pragma unroll 4
        for (int c = 0; c < SPAN; c++) {
            float p0 = pr0[c];
            float p1 = pr1[c];
            float4 vv = *reinterpret_cast<const float4*>(sm + V_OFF + c * KSTR + cq * 4);
            a0.x += p0 * vv.x; a0.y += p0 * vv.y; a0.z += p0 * vv.z; a0.w += p0 * vv.w;
            a1.x += p1 * vv.x; a1.y += p1 * vv.y; a1.z += p1 * vv.z; a1.w += p1 * vv.w;
        }
        float4* out4 = reinterpret_cast<float4*>(out);
        out4[(size_t)(h * SQ + t0 + R0) * 16 + cq] = a0;
        out4[(size_t)(h * SQ + t0 + R1) * 16 + cq] = a1;
    }

    // ---------------- Phase C: stream full attn rows (band + zeros) ----------------
    if (attn != nullptr) {
        float4* attn4 = reinterpret_cast<float4*>(attn);
        const float4 z4 = make_float4(0.f, 0.f, 0.f, 0.f);
        #pragma unroll 1
        for (int idx = tid; idx < TQ * (SQ / 4); idx += THREADS) {
            int r   = idx >> 10;             // local row
            int q4i = idx & 1023;            // float4 index within 4096-wide row
            int c0  = q4i * 4 - span_start;  // span col of first element (multiple of 4)
            float4 val = z4;
            if (c0 + 3 >= 0 && c0 < SPAN) {
                const float* pr = sm + P_OFF + r * PSTR;
                if (c0 >= 0 && c0 + 3 < SPAN) {
                    val = *reinterpret_cast<const float4*>(pr + c0);  // aligned: c0 % 4 == 0
                } else {
                    if (c0     >= 0 && c0     < SPAN) val.x = pr[c0];
                    if (c0 + 1 >= 0 && c0 + 1 < SPAN) val.y = pr[c0 + 1];
                    if (c0 + 2 >= 0 && c0 + 2 < SPAN) val.z = pr[c0 + 2];
                    if (c0 + 3 >= 0 && c0 + 3 < SPAN) val.w = pr[c0 + 3];
                }
            }
            attn4[(size_t)(h * SQ + t0 + r) * (SQ / 4) + q4i] = val;
        }
    }
}

extern "C" void kernel_launch(void* const* d_in, const int* in_sizes, int n_in,
                              void* d_out, int out_size) {
    const float* q = (const float*)d_in[0];
    const float* k = (const float*)d_in[1];
    const float* v = (const float*)d_in[2];
    float* out = (float*)d_out;

    const long long OUT_ELEMS = (long long)HH * SQ * DD;  // 4,194,304
    // Output tuple is (out, attn) flattened; guard in case only `out` is compared.
    float* attn = ((long long)out_size > OUT_ELEMS) ? (out + OUT_ELEMS) : nullptr;

    cudaFuncSetAttribute(win_attn_kernel,
                         cudaFuncAttributeMaxDynamicSharedMemorySize, SMEM_BYTES);

    dim3 grid(SQ / TQ, HH);
    win_attn_kernel<<<grid, THREADS, SMEM_BYTES>>>(q, k, v, out, attn);
}